// round 15
// baseline (speedup 1.0000x reference)
#include <cuda_runtime.h>
#include <math.h>

#define HID   1024
#define BSZ   16
#define NOPT  4
#define ROWS  (BSZ*NOPT)    // 64
#define TRUN  2
#define SEQ   1536
#define PLEN  512
#define QLEN  128

#define KSPLIT 32
#define KCHUNK (HID/KSPLIT)   // 32
#define NTILE  64

// Scratch (device globals — no allocation allowed).
// h1/h2 are pure accumulators: zeroed by prep each call, biases folded into
// the consumers' loads.
__device__ float g_feats[ROWS*HID];
__device__ float g_h1[ROWS*HID];
__device__ float g_h2[ROWS*HID];

// ---------------------------------------------------------------------------
// PDL + f32x2 helpers
// ---------------------------------------------------------------------------
__device__ __forceinline__ void pdl_launch_dependents() {
    asm volatile("griddepcontrol.launch_dependents;");
}
__device__ __forceinline__ void pdl_wait() {
    asm volatile("griddepcontrol.wait;" ::: "memory");
}
__device__ __forceinline__ void fma_f32x2(unsigned long long& acc,
                                          unsigned long long a,
                                          unsigned long long b) {
    asm("fma.rn.f32x2 %0, %1, %2, %0;" : "+l"(acc) : "l"(a), "l"(b));
}
__device__ __forceinline__ float lo_f(unsigned long long v) {
    return __uint_as_float((unsigned)(v & 0xFFFFFFFFull));
}
__device__ __forceinline__ float hi_f(unsigned long long v) {
    return __uint_as_float((unsigned)(v >> 32));
}
__device__ __forceinline__ long long opt_at(const void* p, bool is64, int i) {
    if (is64) return ((const long long*)p)[i];
    return (long long)((const int*)p)[i];
}

// ---------------------------------------------------------------------------
// 1) prep (64 CTAs, one feats row each): embedding gather PRE-wait (overlaps
//    the previous replay's tail), then post-wait: store feats, zero h1/h2
//    rows, zero the loss slot.
// ---------------------------------------------------------------------------
__global__ void __launch_bounds__(256)
prep_kernel(const float* __restrict__ emb, const void* __restrict__ opt_length,
            float* __restrict__ out, int out_size) {
    pdl_launch_dependents();

    const int row = blockIdx.x;      // b*NOPT + o
    const int tid = threadIdx.x;
    const int b = row >> 2, o = row & 3;

    bool is64 = (((const int*)opt_length)[1] == 0);
    long long cs = 0;
    for (int i = 0; i <= o; i++) cs += opt_at(opt_length, is64, i);
    int ohead = PLEN + QLEN + (int)cs;
    int otail = ohead + (int)opt_at(opt_length, is64, o + 1) - 1;
    int pos[6] = {0, PLEN - 1, PLEN, PLEN + QLEN - 1, ohead, otail};

    const int h4 = tid * 4;
    float4 acc = make_float4(0.f, 0.f, 0.f, 0.f);
    #pragma unroll
    for (int t = 0; t < TRUN; t++) {
        const float* base = emb + (size_t)(t * BSZ + b) * SEQ * HID;
        #pragma unroll
        for (int p = 0; p < 6; p++) {
            float4 v = *(const float4*)(base + (size_t)pos[p] * HID + h4);
            acc.x += v.x; acc.y += v.y; acc.z += v.z; acc.w += v.w;
        }
    }
    const float s = 0.25f;
    float4 f = make_float4(acc.x * s, acc.y * s, acc.z * s, acc.w * s);

    pdl_wait();   // previous replay's gemv has finished reading h2

    *(float4*)(g_feats + (size_t)row * HID + h4) = f;
    const float4 z = make_float4(0.f, 0.f, 0.f, 0.f);
    *(float4*)(g_h1 + (size_t)row * HID + h4) = z;
    *(float4*)(g_h2 + (size_t)row * HID + h4) = z;

    if (row == 0 && tid == 0) {
        if (out_size == 1)             out[0] = 0.f;
        else if (out_size >= ROWS + 1) out[ROWS] = 0.f;
    }
}

// ---------------------------------------------------------------------------
// 2) Split-K GEMM: 64x64 tile, K-chunk 32, grid (16,32)=512 CTAs, 256 thr,
//    dup-A smem (11 inst/k), REDG.v4 epilogue onto ZEROED accumulator.
//    LAYER==1 applies relu(A + b1) on load (bias folded).
//    PDL: launch_dependents at entry; W tile loaded pre-wait.
// ---------------------------------------------------------------------------
template <int LAYER>
__global__ void __launch_bounds__(256, 4)
gemm_kernel(const float* __restrict__ W, const float* __restrict__ bias) {
    __shared__ float2 As2[KCHUNK][66];   // [k][row] duplicated (a,a), pad 2
    __shared__ float  Ws[KCHUNK][64];    // [k][col]

    pdl_launch_dependents();

    const float* A  = (LAYER == 0) ? g_feats : g_h1;
    float*      out = (LAYER == 0) ? g_h1    : g_h2;

    const int n0  = blockIdx.x * NTILE;
    const int k0  = blockIdx.y * KCHUNK;
    const int tid = threadIdx.x;

    // --- pre-wait prologue: W tile + bias slice (independent) ---
    {
        int c4 = (tid & 15) * 4;
        int kk = tid >> 4;
        #pragma unroll
        for (int i = 0; i < 2; i++) {
            int k = kk + i * 16;
            *(float4*)&Ws[k][c4] =
                *(const float4*)(W + (size_t)(k0 + k) * HID + n0 + c4);
        }
    }
    const int kk4 = (tid & 7) * 4;      // 0..28
    const int r   = tid >> 3;           // 0..31
    float4 bv4 = make_float4(0.f, 0.f, 0.f, 0.f);
    if (LAYER == 1) bv4 = *(const float4*)(bias + k0 + kk4);

    pdl_wait();                // predecessor's writes now visible

    // --- A tile (dependent), duplicated-transposed; LAYER1: relu(A + b1) ---
    #pragma unroll
    for (int rr = 0; rr < 2; rr++) {
        int row = r + rr * 32;
        float4 v = *(const float4*)(A + (size_t)row * HID + k0 + kk4);
        if (LAYER == 1) {
            v.x = fmaxf(v.x + bv4.x, 0.f); v.y = fmaxf(v.y + bv4.y, 0.f);
            v.z = fmaxf(v.z + bv4.z, 0.f); v.w = fmaxf(v.w + bv4.w, 0.f);
        }
        As2[kk4 + 0][row] = make_float2(v.x, v.x);
        As2[kk4 + 1][row] = make_float2(v.y, v.y);
        As2[kk4 + 2][row] = make_float2(v.z, v.z);
        As2[kk4 + 3][row] = make_float2(v.w, v.w);
    }
    __syncthreads();

    const int c0 = (tid & 15) * 4;
    const int r0 = (tid >> 4) * 4;

    unsigned long long acc[4][2] = {};
    #pragma unroll
    for (int kk = 0; kk < KCHUNK; kk++) {
        ulonglong2 wq  = *(const ulonglong2*)&Ws[kk][c0];       // 2 packed col-pairs
        ulonglong2 a01 = *(const ulonglong2*)&As2[kk][r0 + 0];  // rows r0,r0+1 dup
        ulonglong2 a23 = *(const ulonglong2*)&As2[kk][r0 + 2];  // rows r0+2,r0+3

        fma_f32x2(acc[0][0], a01.x, wq.x); fma_f32x2(acc[0][1], a01.x, wq.y);
        fma_f32x2(acc[1][0], a01.y, wq.x); fma_f32x2(acc[1][1], a01.y, wq.y);
        fma_f32x2(acc[2][0], a23.x, wq.x); fma_f32x2(acc[2][1], a23.x, wq.y);
        fma_f32x2(acc[3][0], a23.y, wq.x); fma_f32x2(acc[3][1], a23.y, wq.y);
    }

    #pragma unroll
    for (int i = 0; i < 4; i++) {
        float* p = out + (size_t)(r0 + i) * HID + n0 + c0;
        asm volatile("red.global.add.v4.f32 [%0], {%1, %2, %3, %4};"
                     :: "l"(p),
                        "f"(lo_f(acc[i][0])), "f"(hi_f(acc[i][0])),
                        "f"(lo_f(acc[i][1])), "f"(hi_f(acc[i][1])) : "memory");
    }
}

// ---------------------------------------------------------------------------
// 3) gemv+loss, batch-per-CTA (16 CTAs x 256 thr), sync-free loss red.add.
//    b2 folded: logits = relu(h2 + b2) . W3.  W3/b2 loaded pre-wait.
// ---------------------------------------------------------------------------
__global__ void __launch_bounds__(256)
gemv_loss_kernel(const float* __restrict__ W3, const float* __restrict__ b2,
                 const int* __restrict__ y,
                 float* __restrict__ out, int out_size) {
    __shared__ float red[8];
    __shared__ float lsh[NOPT];

    const int b    = blockIdx.x;        // batch 0..15
    const int tid  = threadIdx.x;
    const int o    = tid >> 6;          // option 0..3
    const int lane = tid & 63;

    // --- pre-wait prologue: W3 + b2 into registers ---
    float4 wv[4], bv[4];
    #pragma unroll
    for (int i = 0; i < 4; i++) {
        wv[i] = *(const float4*)(W3 + (lane + i * 64) * 4);
        bv[i] = *(const float4*)(b2 + (lane + i * 64) * 4);
    }

    pdl_wait();                // h2 now complete

    const float* h = g_h2 + (size_t)(b * NOPT + o) * HID;
    float s = 0.f;
    #pragma unroll
    for (int i = 0; i < 4; i++) {       // 64 lanes * 4 iters * float4 = 1024
        int k = (lane + i * 64) * 4;
        float4 hv = *(const float4*)(h + k);
        s += fmaxf(hv.x + bv[i].x, 0.f) * wv[i].x
           + fmaxf(hv.y + bv[i].y, 0.f) * wv[i].y
           + fmaxf(hv.z + bv[i].z, 0.f) * wv[i].z
           + fmaxf(hv.w + bv[i].w, 0.f) * wv[i].w;
    }
    #pragma unroll
    for (int off = 16; off; off >>= 1)
        s += __shfl_down_sync(0xFFFFFFFFu, s, off);
    if ((tid & 31) == 0) red[tid >> 5] = s;
    __syncthreads();

    if (tid < NOPT) lsh[tid] = red[2 * tid] + red[2 * tid + 1];
    __syncthreads();

    if (tid == 0) {
        float l0 = lsh[0], l1 = lsh[1], l2 = lsh[2], l3 = lsh[3];
        if (out_size >= ROWS) {
            out[b * NOPT + 0] = l0; out[b * NOPT + 1] = l1;
            out[b * NOPT + 2] = l2; out[b * NOPT + 3] = l3;
        }
        float m  = fmaxf(fmaxf(l0, l1), fmaxf(l2, l3));
        float se = expf(l0 - m) + expf(l1 - m) + expf(l2 - m) + expf(l3 - m);
        float lse = m + logf(se);
        int yy = y[b];
        float ly = (yy == 0) ? l0 : (yy == 1) ? l1 : (yy == 2) ? l2 : l3;
        float contrib = -(ly - lse) * (1.0f / (float)BSZ);

        float* dst = (out_size == 1) ? out
                   : (out_size >= ROWS + 1) ? (out + ROWS) : nullptr;
        if (dst)
            asm volatile("red.global.add.f32 [%0], %1;"
                         :: "l"(dst), "f"(contrib) : "memory");
    }
    pdl_launch_dependents();   // next replay's prep may begin its gather
}

// ---------------------------------------------------------------------------
// Launch — 4 PDL-chained kernels
// inputs: 0=embeddings 1=W1 2=b1 3=W2 4=b2 5=W3 6=y 7=opt_length
// ---------------------------------------------------------------------------
template <typename F, typename... Args>
static void launch_pdl(F* func, dim3 grid, dim3 block, Args... args) {
    cudaLaunchConfig_t cfg = {};
    cfg.gridDim  = grid;
    cfg.blockDim = block;
    cfg.stream   = 0;
    cudaLaunchAttribute attr[1];
    attr[0].id = cudaLaunchAttributeProgrammaticStreamSerialization;
    attr[0].val.programmaticStreamSerializationAllowed = 1;
    cfg.attrs    = attr;
    cfg.numAttrs = 1;
    cudaLaunchKernelEx(&cfg, func, args...);
}

extern "C" void kernel_launch(void* const* d_in, const int* in_sizes, int n_in,
                              void* d_out, int out_size) {
    const float* emb = (const float*)d_in[0];
    const float* W1  = (const float*)d_in[1];
    const float* b1  = (const float*)d_in[2];
    const float* W2  = (const float*)d_in[3];
    const float* b2  = (const float*)d_in[4];
    const float* W3  = (const float*)d_in[5];
    const int*   y   = (const int*)d_in[6];
    const void*  opt = (const void*)d_in[7];
    float* out = (float*)d_out;

    launch_pdl(prep_kernel, dim3(ROWS), dim3(256), emb, opt, out, out_size);
    launch_pdl(gemm_kernel<0>, dim3(16, KSPLIT), dim3(256), W1, b1);
    launch_pdl(gemm_kernel<1>, dim3(16, KSPLIT), dim3(256), W2, b1);
    launch_pdl(gemv_loss_kernel, dim3(BSZ), dim3(256), W3, b2, y, out, out_size);
}

// round 16
// speedup vs baseline: 1.0796x; 1.0796x over previous
#include <cuda_runtime.h>
#include <math.h>

#define HID   1024
#define BSZ   16
#define NOPT  4
#define ROWS  (BSZ*NOPT)    // 64
#define TRUN  2
#define SEQ   1536
#define PLEN  512
#define QLEN  128

#define KSPLIT 32
#define KCHUNK (HID/KSPLIT)   // 32
#define NTILE  64

// Scratch (device globals — no allocation allowed)
__device__ float g_feats[ROWS*HID];
__device__ float g_h1[ROWS*HID];
__device__ float g_h2[ROWS*HID];

// ---------------------------------------------------------------------------
// PDL + f32x2 helpers
// ---------------------------------------------------------------------------
__device__ __forceinline__ void pdl_launch_dependents() {
    asm volatile("griddepcontrol.launch_dependents;");
}
__device__ __forceinline__ void pdl_wait() {
    asm volatile("griddepcontrol.wait;" ::: "memory");
}
__device__ __forceinline__ void fma_f32x2(unsigned long long& acc,
                                          unsigned long long a,
                                          unsigned long long b) {
    asm("fma.rn.f32x2 %0, %1, %2, %0;" : "+l"(acc) : "l"(a), "l"(b));
}
__device__ __forceinline__ float lo_f(unsigned long long v) {
    return __uint_as_float((unsigned)(v & 0xFFFFFFFFull));
}
__device__ __forceinline__ float hi_f(unsigned long long v) {
    return __uint_as_float((unsigned)(v >> 32));
}
__device__ __forceinline__ long long opt_at(const void* p, bool is64, int i) {
    if (is64) return ((const long long*)p)[i];
    return (long long)((const int*)p)[i];
}

// ---------------------------------------------------------------------------
// 1) prep (320 CTAs): blocks [0,256) bias-init h1/h2; blocks [256,320) feats.
//    Zeroes the loss output slot. Signals dependents immediately.
// ---------------------------------------------------------------------------
__global__ void __launch_bounds__(256)
prep_kernel(const float* __restrict__ emb, const void* __restrict__ opt_length,
            const float* __restrict__ b1, const float* __restrict__ b2,
            float* __restrict__ out, int out_size) {
    pdl_launch_dependents();   // let gemm0 start its W1 prologue now

    if (blockIdx.x == 0 && threadIdx.x == 0) {
        if (out_size == 1)             out[0] = 0.f;
        else if (out_size >= ROWS + 1) out[ROWS] = 0.f;
    }

    if (blockIdx.x < 256) {
        int i = blockIdx.x * 256 + threadIdx.x;     // 0..65535
        int j = i & (HID - 1);
        g_h1[i] = b1[j];
        g_h2[i] = b2[j];
        return;
    }
    int row = blockIdx.x - 256;      // b*NOPT + o
    int b = row >> 2, o = row & 3;

    bool is64 = (((const int*)opt_length)[1] == 0);
    long long cs = 0;
    for (int i = 0; i <= o; i++) cs += opt_at(opt_length, is64, i);
    int ohead = PLEN + QLEN + (int)cs;
    int otail = ohead + (int)opt_at(opt_length, is64, o + 1) - 1;
    int pos[6] = {0, PLEN - 1, PLEN, PLEN + QLEN - 1, ohead, otail};

    int h4 = threadIdx.x * 4;
    float4 acc = make_float4(0.f, 0.f, 0.f, 0.f);
    #pragma unroll
    for (int t = 0; t < TRUN; t++) {
        const float* base = emb + (size_t)(t * BSZ + b) * SEQ * HID;
        #pragma unroll
        for (int p = 0; p < 6; p++) {
            float4 v = *(const float4*)(base + (size_t)pos[p] * HID + h4);
            acc.x += v.x; acc.y += v.y; acc.z += v.z; acc.w += v.w;
        }
    }
    const float s = 0.25f;
    *(float4*)(g_feats + (size_t)row * HID + h4) =
        make_float4(acc.x * s, acc.y * s, acc.z * s, acc.w * s);
}

// ---------------------------------------------------------------------------
// 2) Split-K GEMM (R14/R4 geometry): 64x64 tile, K-chunk 32, grid (16,32)=
//    512 CTAs, 256 thr, dup-A smem (11 inst/k), REDG.v4 epilogue onto
//    bias-initialized out. PDL: signal at ENTRY; W tile loaded pre-wait.
// ---------------------------------------------------------------------------
template <int LAYER>
__global__ void __launch_bounds__(256, 4)
gemm_kernel(const float* __restrict__ W) {
    __shared__ float2 As2[KCHUNK][66];   // [k][row] duplicated (a,a), pad 2
    __shared__ float  Ws[KCHUNK][64];    // [k][col]

    pdl_launch_dependents();   // earliest legal point: successor prologue is independent

    const float* A  = (LAYER == 0) ? g_feats : g_h1;
    float*      out = (LAYER == 0) ? g_h1    : g_h2;

    const int n0  = blockIdx.x * NTILE;
    const int k0  = blockIdx.y * KCHUNK;
    const int tid = threadIdx.x;

    // --- PDL prologue: W tile (independent of predecessor) ---
    {
        int c4 = (tid & 15) * 4;
        int kk = tid >> 4;
        #pragma unroll
        for (int i = 0; i < 2; i++) {
            int k = kk + i * 16;
            *(float4*)&Ws[k][c4] =
                *(const float4*)(W + (size_t)(k0 + k) * HID + n0 + c4);
        }
    }
    pdl_wait();                // predecessor's writes now visible

    // --- A tile (dependent), duplicated-transposed ---
    {
        int kk4 = (tid & 7) * 4;      // 0..28
        int r   = tid >> 3;           // 0..31
        #pragma unroll
        for (int rr = 0; rr < 2; rr++) {
            int row = r + rr * 32;
            float4 v = *(const float4*)(A + (size_t)row * HID + k0 + kk4);
            if (LAYER == 1) {
                v.x = fmaxf(v.x, 0.f); v.y = fmaxf(v.y, 0.f);
                v.z = fmaxf(v.z, 0.f); v.w = fmaxf(v.w, 0.f);
            }
            As2[kk4 + 0][row] = make_float2(v.x, v.x);
            As2[kk4 + 1][row] = make_float2(v.y, v.y);
            As2[kk4 + 2][row] = make_float2(v.z, v.z);
            As2[kk4 + 3][row] = make_float2(v.w, v.w);
        }
    }
    __syncthreads();

    const int c0 = (tid & 15) * 4;
    const int r0 = (tid >> 4) * 4;

    unsigned long long acc[4][2] = {};
    #pragma unroll
    for (int kk = 0; kk < KCHUNK; kk++) {
        ulonglong2 wq  = *(const ulonglong2*)&Ws[kk][c0];       // 2 packed col-pairs
        ulonglong2 a01 = *(const ulonglong2*)&As2[kk][r0 + 0];  // rows r0,r0+1 dup
        ulonglong2 a23 = *(const ulonglong2*)&As2[kk][r0 + 2];  // rows r0+2,r0+3

        fma_f32x2(acc[0][0], a01.x, wq.x); fma_f32x2(acc[0][1], a01.x, wq.y);
        fma_f32x2(acc[1][0], a01.y, wq.x); fma_f32x2(acc[1][1], a01.y, wq.y);
        fma_f32x2(acc[2][0], a23.x, wq.x); fma_f32x2(acc[2][1], a23.x, wq.y);
        fma_f32x2(acc[3][0], a23.y, wq.x); fma_f32x2(acc[3][1], a23.y, wq.y);
    }

    #pragma unroll
    for (int i = 0; i < 4; i++) {
        float* p = out + (size_t)(r0 + i) * HID + n0 + c0;
        asm volatile("red.global.add.v4.f32 [%0], {%1, %2, %3, %4};"
                     :: "l"(p),
                        "f"(lo_f(acc[i][0])), "f"(hi_f(acc[i][0])),
                        "f"(lo_f(acc[i][1])), "f"(hi_f(acc[i][1])) : "memory");
    }
}

// ---------------------------------------------------------------------------
// 3) gemv+loss, batch-per-CTA (16 CTAs x 256 thr), sync-free loss red.add.
//    PDL: W3 fetched into regs BEFORE the wait; signal dependents at end
//    (lets a following replay's prep begin early if replays chain).
// ---------------------------------------------------------------------------
__global__ void __launch_bounds__(256)
gemv_loss_kernel(const float* __restrict__ W3, const int* __restrict__ y,
                 float* __restrict__ out, int out_size) {
    __shared__ float red[8];
    __shared__ float lsh[NOPT];

    const int b    = blockIdx.x;        // batch 0..15
    const int tid  = threadIdx.x;
    const int o    = tid >> 6;          // option 0..3
    const int lane = tid & 63;

    // --- PDL prologue: W3 (independent) into registers ---
    float4 wv[4];
    #pragma unroll
    for (int i = 0; i < 4; i++)
        wv[i] = *(const float4*)(W3 + (lane + i * 64) * 4);

    pdl_wait();                // h2 now complete

    const float* h = g_h2 + (size_t)(b * NOPT + o) * HID;
    float s = 0.f;
    #pragma unroll
    for (int i = 0; i < 4; i++) {       // 64 lanes * 4 iters * float4 = 1024
        int k = (lane + i * 64) * 4;
        float4 hv = *(const float4*)(h + k);
        s += fmaxf(hv.x, 0.f) * wv[i].x + fmaxf(hv.y, 0.f) * wv[i].y
           + fmaxf(hv.z, 0.f) * wv[i].z + fmaxf(hv.w, 0.f) * wv[i].w;
    }
    #pragma unroll
    for (int off = 16; off; off >>= 1)
        s += __shfl_down_sync(0xFFFFFFFFu, s, off);
    if ((tid & 31) == 0) red[tid >> 5] = s;
    __syncthreads();

    if (tid < NOPT) lsh[tid] = red[2 * tid] + red[2 * tid + 1];
    __syncthreads();

    if (tid == 0) {
        float l0 = lsh[0], l1 = lsh[1], l2 = lsh[2], l3 = lsh[3];
        if (out_size >= ROWS) {
            out[b * NOPT + 0] = l0; out[b * NOPT + 1] = l1;
            out[b * NOPT + 2] = l2; out[b * NOPT + 3] = l3;
        }
        float m  = fmaxf(fmaxf(l0, l1), fmaxf(l2, l3));
        float se = expf(l0 - m) + expf(l1 - m) + expf(l2 - m) + expf(l3 - m);
        float lse = m + logf(se);
        int yy = y[b];
        float ly = (yy == 0) ? l0 : (yy == 1) ? l1 : (yy == 2) ? l2 : l3;
        float contrib = -(ly - lse) * (1.0f / (float)BSZ);

        float* dst = (out_size == 1) ? out
                   : (out_size >= ROWS + 1) ? (out + ROWS) : nullptr;
        if (dst)
            asm volatile("red.global.add.f32 [%0], %1;"
                         :: "l"(dst), "f"(contrib) : "memory");
    }
    pdl_launch_dependents();
}

// ---------------------------------------------------------------------------
// Launch — 4 kernels, PDL-chained
// inputs: 0=embeddings 1=W1 2=b1 3=W2 4=b2 5=W3 6=y 7=opt_length
// ---------------------------------------------------------------------------
template <typename F, typename... Args>
static void launch_pdl(F* func, dim3 grid, dim3 block, Args... args) {
    cudaLaunchConfig_t cfg = {};
    cfg.gridDim  = grid;
    cfg.blockDim = block;
    cfg.stream   = 0;
    cudaLaunchAttribute attr[1];
    attr[0].id = cudaLaunchAttributeProgrammaticStreamSerialization;
    attr[0].val.programmaticStreamSerializationAllowed = 1;
    cfg.attrs    = attr;
    cfg.numAttrs = 1;
    cudaLaunchKernelEx(&cfg, func, args...);
}

extern "C" void kernel_launch(void* const* d_in, const int* in_sizes, int n_in,
                              void* d_out, int out_size) {
    const float* emb = (const float*)d_in[0];
    const float* W1  = (const float*)d_in[1];
    const float* b1  = (const float*)d_in[2];
    const float* W2  = (const float*)d_in[3];
    const float* b2  = (const float*)d_in[4];
    const float* W3  = (const float*)d_in[5];
    const int*   y   = (const int*)d_in[6];
    const void*  opt = (const void*)d_in[7];
    float* out = (float*)d_out;

    prep_kernel<<<320, 256>>>(emb, opt, b1, b2, out, out_size);
    launch_pdl(gemm_kernel<0>, dim3(16, KSPLIT), dim3(256), W1);
    launch_pdl(gemm_kernel<1>, dim3(16, KSPLIT), dim3(256), W2);
    launch_pdl(gemv_loss_kernel, dim3(BSZ), dim3(256), W3, y, out, out_size);
}